// round 9
// baseline (speedup 1.0000x reference)
#include <cuda_runtime.h>
#include <cuda_bf16.h>
#include <cuda_fp16.h>
#include <math.h>
#include <stdint.h>

// ---------------- problem constants ----------------
#define BATCH   4
#define LEN     2048
#define HEADS   32
#define PDIM    64
#define NSTATE  32
#define KCONV   4
#define DMODEL  2048              // HEADS*PDIM
#define CONVDIM 2112              // DMODEL + 2*NSTATE
#define PROJ    4192              // DMODEL + CONVDIM + HEADS
#define PROJPAD 4224              // PROJ padded to 128 multiple
#define MROWS   (BATCH*LEN)       // 8192
#define EPS     1e-6f

// ---------------- scratch (static device globals) ----------------
__device__ float g_proj[(size_t)MROWS * PROJ];
__device__ float g_xs  [(size_t)MROWS * DMODEL];
__device__ float g_Bm  [MROWS * NSTATE];
__device__ float g_Cm  [MROWS * NSTATE];
__device__ float g_dt  [MROWS * HEADS];
__device__ float g_dA  [MROWS * HEADS];
__device__ float g_ys  [(size_t)MROWS * DMODEL];

__device__ __half g_xh [(size_t)MROWS * DMODEL];      // x hi (fp16)
__device__ __half g_xl [(size_t)MROWS * DMODEL];      // x residual (fp16)
__device__ __half g_W1t[(size_t)PROJPAD * DMODEL];    // W_in^T fp16
__device__ __half g_W2t[(size_t)DMODEL * DMODEL];     // W_out^T fp16
__device__ __half g_yh [(size_t)MROWS * DMODEL];      // y hi
__device__ __half g_yl [(size_t)MROWS * DMODEL];      // y residual

// ==================== PTX helpers ====================
__device__ __forceinline__ uint32_t smem_u32(const void* p) {
    uint32_t a;
    asm("{ .reg .u64 t; cvta.to.shared.u64 t, %1; cvt.u32.u64 %0, t; }"
        : "=r"(a) : "l"(p));
    return a;
}
__device__ __forceinline__ void cp16(uint32_t s, const void* g) {
    asm volatile("cp.async.cg.shared.global [%0], [%1], 16;" :: "r"(s), "l"(g));
}
#define CP_COMMIT() asm volatile("cp.async.commit_group;" ::: "memory")
#define CP_WAIT1()  asm volatile("cp.async.wait_group 1;"  ::: "memory")

__device__ __forceinline__ void ldsm4(uint32_t* r, uint32_t addr) {
    asm volatile("ldmatrix.sync.aligned.m8n8.x4.shared.b16 {%0,%1,%2,%3}, [%4];"
        : "=r"(r[0]), "=r"(r[1]), "=r"(r[2]), "=r"(r[3]) : "r"(addr));
}
__device__ __forceinline__ void mma16816(float* d, const uint32_t* a, const uint32_t* b) {
    asm volatile(
        "mma.sync.aligned.m16n8k16.row.col.f32.f16.f16.f32 "
        "{%0,%1,%2,%3}, {%4,%5,%6,%7}, {%8,%9}, {%0,%1,%2,%3};"
        : "+f"(d[0]), "+f"(d[1]), "+f"(d[2]), "+f"(d[3])
        : "r"(a[0]), "r"(a[1]), "r"(a[2]), "r"(a[3]), "r"(b[0]), "r"(b[1]));
}

// ==================== fp16 2-term tensor-core GEMM ====================
// C[M, Nreal] = A[M,K] @ W[K,N]; A = Ah + Al (fp16 pair, exact to 2^-22),
// B^T = Bh [N,K] fp16 (rounded). C = Ah*Bh + Al*Bh = A*Bh.
#define BM 128
#define BN 128
#define BK 32
#define LDS 40                    // smem row stride in fp16 (80 B) - conflict-free
#define TILE_B (BM * LDS * 2)     // 10240 bytes per matrix tile
#define STAGE_B (3 * TILE_B)      // 30720 bytes (Ah, Al, Bh)
#define NSTAGE 3
#define SMEM_GEMM (NSTAGE * STAGE_B)   // 92160 bytes

__device__ __forceinline__ void load_stage(
    uint32_t sbase, const __half* Ah, const __half* Al, const __half* Bh,
    int m0, int n0, int k0, int tid)
{
    const int row  = tid >> 1;
    const int half = tid & 1;
    const uint32_t soff = (uint32_t)(row * LDS + half * 16) * 2;   // bytes
    const size_t ga = (size_t)(m0 + row) * DMODEL + k0 + half * 16;
    const size_t gb = (size_t)(n0 + row) * DMODEL + k0 + half * 16;
    cp16(sbase + 0*TILE_B + soff,      Ah + ga);
    cp16(sbase + 0*TILE_B + soff + 16, Ah + ga + 8);
    cp16(sbase + 1*TILE_B + soff,      Al + ga);
    cp16(sbase + 1*TILE_B + soff + 16, Al + ga + 8);
    cp16(sbase + 2*TILE_B + soff,      Bh + gb);
    cp16(sbase + 2*TILE_B + soff + 16, Bh + gb + 8);
}

__global__ __launch_bounds__(256, 2)
void mma_gemm_kernel(const __half* __restrict__ Ah,
                     const __half* __restrict__ Al,
                     const __half* __restrict__ Bh,
                     const float* __restrict__ bias,
                     float* __restrict__ C, int Nreal)
{
    extern __shared__ char smem[];
    const uint32_t sb = smem_u32(smem);
    const int tid  = threadIdx.x;
    const int wid  = tid >> 5, lane = tid & 31;
    const int wm   = wid & 1;         // 2 m-warps (64 rows each)
    const int wn   = wid >> 1;        // 4 n-warps (32 cols each)
    const int m0   = blockIdx.y * BM;
    const int n0   = blockIdx.x * BN;

    // ldmatrix lane-relative byte offsets (verified in R6)
    const uint32_t a_loff = (uint32_t)((lane & 15) * LDS + (lane >> 4) * 8) * 2;
    const int b_q = lane >> 3, b_r = lane & 7;
    const uint32_t b_loff = (uint32_t)(((b_q >> 1) * 8 + b_r) * LDS + (b_q & 1) * 8) * 2;

    float acc[4][4][4];
    #pragma unroll
    for (int i = 0; i < 4; ++i)
        #pragma unroll
        for (int j = 0; j < 4; ++j)
            #pragma unroll
            for (int r = 0; r < 4; ++r) acc[i][j][r] = 0.f;

    load_stage(sb,           Ah, Al, Bh, m0, n0, 0,  tid); CP_COMMIT();
    load_stage(sb + STAGE_B, Ah, Al, Bh, m0, n0, BK, tid); CP_COMMIT();

    const int iters = DMODEL / BK;   // 64
    for (int it = 0; it < iters; ++it) {
        CP_WAIT1();                  // stage `it` complete; `it+1` may be in flight
        __syncthreads();             // also protects buffer (it+2)%3 == (it-1)%3

        // prefetch stage it+2 (overlaps with compute below)
        const int kn = (it + NSTAGE - 1) * BK;
        if (kn < DMODEL)
            load_stage(sb + (uint32_t)((it + NSTAGE - 1) % NSTAGE) * STAGE_B,
                       Ah, Al, Bh, m0, n0, kn, tid);
        CP_COMMIT();

        const uint32_t base = sb + (uint32_t)(it % NSTAGE) * STAGE_B;
        const uint32_t aAh  = base + (uint32_t)(wm * 64 * LDS) * 2 + a_loff;
        const uint32_t aAl  = aAh + TILE_B;
        const uint32_t bBh  = base + 2*TILE_B + (uint32_t)(wn * 32 * LDS) * 2 + b_loff;

        #pragma unroll
        for (int ks = 0; ks < 2; ++ks) {
            const uint32_t koff = ks * 32;           // 16 fp16 = 32 bytes
            uint32_t bh[4][2];
            #pragma unroll
            for (int jp = 0; jp < 2; ++jp) {
                uint32_t t4[4];
                ldsm4(t4, bBh + (uint32_t)(jp * 16 * LDS) * 2 + koff);
                bh[2*jp][0]   = t4[0]; bh[2*jp][1]   = t4[1];
                bh[2*jp+1][0] = t4[2]; bh[2*jp+1][1] = t4[3];
            }
            #pragma unroll
            for (int i = 0; i < 4; ++i) {
                uint32_t ah[4], al[4];
                ldsm4(ah, aAh + (uint32_t)(i * 16 * LDS) * 2 + koff);
                ldsm4(al, aAl + (uint32_t)(i * 16 * LDS) * 2 + koff);
                #pragma unroll
                for (int j = 0; j < 4; ++j) {
                    mma16816(acc[i][j], ah, bh[j]);
                    mma16816(acc[i][j], al, bh[j]);
                }
            }
        }
    }

    // ---- epilogue ----
    const int r0 = lane >> 2;
    const int c0 = (lane & 3) * 2;
    #pragma unroll
    for (int i = 0; i < 4; ++i) {
        const int row = m0 + wm * 64 + i * 16 + r0;
        #pragma unroll
        for (int j = 0; j < 4; ++j) {
            const int col = n0 + wn * 32 + j * 8 + c0;
            if (col < Nreal) {
                float b0 = 0.f, b1 = 0.f;
                if (bias) { b0 = bias[col]; b1 = bias[col + 1]; }
                float* p0 = C + (size_t)row * Nreal + col;
                float* p1 = C + (size_t)(row + 8) * Nreal + col;
                p0[0] = acc[i][j][0] + b0;  p0[1] = acc[i][j][1] + b1;
                p1[0] = acc[i][j][2] + b0;  p1[1] = acc[i][j][3] + b1;
            }
        }
    }
}

// ==================== fp16 split conversions ====================
// x fp32 -> xh + xl (fp16 pair)
__global__ __launch_bounds__(256)
void split_x_kernel(const float* __restrict__ src, __half* __restrict__ h,
                    __half* __restrict__ l, size_t n4)
{
    const size_t stride = (size_t)gridDim.x * blockDim.x;
    for (size_t i = (size_t)blockIdx.x * blockDim.x + threadIdx.x; i < n4; i += stride) {
        float4 v = reinterpret_cast<const float4*>(src)[i];
        __half h0 = __float2half_rn(v.x), h1 = __float2half_rn(v.y);
        __half h2 = __float2half_rn(v.z), h3 = __float2half_rn(v.w);
        __half2* hp = reinterpret_cast<__half2*>(h);
        __half2* lp = reinterpret_cast<__half2*>(l);
        hp[i*2]   = __half2(h0, h1);
        hp[i*2+1] = __half2(h2, h3);
        lp[i*2]   = __half2(__float2half_rn(v.x - __half2float(h0)),
                            __float2half_rn(v.y - __half2float(h1)));
        lp[i*2+1] = __half2(__float2half_rn(v.z - __half2float(h2)),
                            __float2half_rn(v.w - __half2float(h3)));
    }
}

// W[K,N] fp32 -> Wt [Npad,K] fp16 (transpose, zero pad rows n>=N)
__global__ __launch_bounds__(256)
void transpose_h_kernel(const float* __restrict__ W,
                        __half* __restrict__ th, int K, int N)
{
    __shared__ float t[32][33];
    const int n0 = blockIdx.x * 32;
    const int k0 = blockIdx.y * 32;
    const int tx = threadIdx.x & 31;
    const int ty = threadIdx.x >> 5;
    #pragma unroll
    for (int i = 0; i < 4; ++i) {
        const int k = k0 + ty + i * 8;
        const int n = n0 + tx;
        t[ty + i * 8][tx] = (n < N) ? W[(size_t)k * N + n] : 0.f;
    }
    __syncthreads();
    #pragma unroll
    for (int i = 0; i < 4; ++i) {
        const int n = n0 + ty + i * 8;
        const int k = k0 + tx;
        th[(size_t)n * K + k] = __float2half_rn(t[tx][ty + i * 8]);
    }
}

// ==================== conv + dt, scan, rmsnorm ====================
__device__ __forceinline__ float silu_f(float x) { return x / (1.f + expf(-x)); }
__device__ __forceinline__ float softplus_f(float x) {
    return x > 20.f ? x : log1pf(expf(x));
}

__global__ void conv_dt_kernel(const float* __restrict__ conv_w,
                               const float* __restrict__ conv_b,
                               const float* __restrict__ A_log,
                               const float* __restrict__ dt_bias)
{
    const int m = blockIdx.x;
    const int l = m & (LEN - 1);
    for (int c = threadIdx.x; c < CONVDIM + HEADS; c += blockDim.x) {
        if (c < CONVDIM) {
            float v = conv_b[c];
            const size_t colbase = (size_t)DMODEL + c;
            #pragma unroll
            for (int k = 0; k < KCONV; ++k) {
                int dl = l - (KCONV - 1) + k;
                if (dl >= 0) {
                    float hv = g_proj[(size_t)(m - (KCONV - 1) + k) * PROJ + colbase];
                    v = fmaf(hv, conv_w[c * KCONV + k], v);
                }
            }
            v = silu_f(v);
            if (c < DMODEL)               g_xs[(size_t)m * DMODEL + c] = v;
            else if (c < DMODEL + NSTATE) g_Bm[m * NSTATE + (c - DMODEL)] = v;
            else                          g_Cm[m * NSTATE + (c - DMODEL - NSTATE)] = v;
        } else {
            const int h = c - CONVDIM;
            float raw = g_proj[(size_t)m * PROJ + (DMODEL + CONVDIM) + h] + dt_bias[h];
            float dt  = softplus_f(raw);
            float A   = -expf(A_log[h]);
            g_dt[m * HEADS + h] = dt;
            g_dA[m * HEADS + h] = expf(dt * A);
        }
    }
}

__global__ __launch_bounds__(256, 4)
void scan_kernel()
{
    const int b = blockIdx.x >> 5;
    const int h = blockIdx.x & 31;
    const int tid = threadIdx.x;
    const int p  = tid >> 2;
    const int ng = tid & 3;

    __shared__ float sx[2][PDIM];
    __shared__ float sB[2][NSTATE];
    __shared__ float sC[2][NSTATE];
    __shared__ float sS[2][2];

    float hreg[8];
    #pragma unroll
    for (int j = 0; j < 8; ++j) hreg[j] = 0.f;

    const int baseRow = b * LEN;
    {
        const int m = baseRow;
        if (tid < 64)        sx[0][tid]      = g_xs[(size_t)m * DMODEL + h * PDIM + tid];
        else if (tid < 96)   sB[0][tid - 64] = g_Bm[m * NSTATE + tid - 64];
        else if (tid < 128)  sC[0][tid - 96] = g_Cm[m * NSTATE + tid - 96];
        else if (tid == 128) sS[0][0]        = g_dA[m * HEADS + h];
        else if (tid == 129) sS[0][1]        = g_dt[m * HEADS + h];
    }
    __syncthreads();

    for (int t = 0; t < LEN; ++t) {
        const int buf = t & 1;
        if (t + 1 < LEN) {
            const int m = baseRow + t + 1;
            const int nb = buf ^ 1;
            if (tid < 64)        sx[nb][tid]      = g_xs[(size_t)m * DMODEL + h * PDIM + tid];
            else if (tid < 96)   sB[nb][tid - 64] = g_Bm[m * NSTATE + tid - 64];
            else if (tid < 128)  sC[nb][tid - 96] = g_Cm[m * NSTATE + tid - 96];
            else if (tid == 128) sS[nb][0]        = g_dA[m * HEADS + h];
            else if (tid == 129) sS[nb][1]        = g_dt[m * HEADS + h];
        }
        const float a   = sS[buf][0];
        const float dtx = sS[buf][1] * sx[buf][p];
        float acc = 0.f;
        #pragma unroll
        for (int j = 0; j < 8; ++j) {
            const int n = ng * 8 + j;
            hreg[j] = fmaf(a, hreg[j], dtx * sB[buf][n]);
            acc = fmaf(hreg[j], sC[buf][n], acc);
        }
        acc += __shfl_xor_sync(0xffffffffu, acc, 1);
        acc += __shfl_xor_sync(0xffffffffu, acc, 2);
        if (ng == 0)
            g_ys[(size_t)(baseRow + t) * DMODEL + h * PDIM + p] = acc;
        __syncthreads();
    }
}

// y = ys + D*xs ; gate ; RMSNorm ; emit fp16 hi/lo pair (feeds GEMM2)
__global__ __launch_bounds__(256)
void gated_rmsnorm_kernel(const float* __restrict__ D_param,
                          const float* __restrict__ norm_w)
{
    const int m = blockIdx.x;
    const int tid = threadIdx.x;
    float v[8];
    float ss = 0.f;

    #pragma unroll
    for (int i = 0; i < 8; ++i) {
        const int d = tid + i * 256;
        const int h = d >> 6;
        float val = g_ys[(size_t)m * DMODEL + d] + D_param[h] * g_xs[(size_t)m * DMODEL + d];
        float g   = g_proj[(size_t)m * PROJ + d];
        val *= silu_f(g);
        v[i] = val;
        ss = fmaf(val, val, ss);
    }
    #pragma unroll
    for (int o = 16; o > 0; o >>= 1) ss += __shfl_xor_sync(0xffffffffu, ss, o);
    __shared__ float red[8];
    if ((tid & 31) == 0) red[tid >> 5] = ss;
    __syncthreads();
    if (tid < 32) {
        float t2 = (tid < 8) ? red[tid] : 0.f;
        #pragma unroll
        for (int o = 4; o > 0; o >>= 1) t2 += __shfl_xor_sync(0xffffffffu, t2, o);
        if (tid == 0) red[0] = t2;
    }
    __syncthreads();
    const float scale = rsqrtf(red[0] / (float)DMODEL + EPS);

    #pragma unroll
    for (int i = 0; i < 8; ++i) {
        const int d = tid + i * 256;
        const float y = v[i] * scale * norm_w[d];
        const __half hh = __float2half_rn(y);
        g_yh[(size_t)m * DMODEL + d] = hh;
        g_yl[(size_t)m * DMODEL + d] = __float2half_rn(y - __half2float(hh));
    }
}

// ==================== host launcher ====================
extern "C" void kernel_launch(void* const* d_in, const int* in_sizes, int n_in,
                              void* d_out, int out_size)
{
    const float* x       = (const float*)d_in[0];
    const float* W_in    = (const float*)d_in[1];
    const float* b_in    = (const float*)d_in[2];
    const float* conv_w  = (const float*)d_in[3];
    const float* conv_b  = (const float*)d_in[4];
    const float* A_log   = (const float*)d_in[5];
    const float* dt_bias = (const float*)d_in[6];
    const float* D_param = (const float*)d_in[7];
    const float* norm_w  = (const float*)d_in[8];
    const float* W_out   = (const float*)d_in[9];
    float* out = (float*)d_out;

    void *p_proj, *p_xh, *p_xl, *p_W1t, *p_W2t, *p_yh, *p_yl;
    cudaGetSymbolAddress(&p_proj, g_proj);
    cudaGetSymbolAddress(&p_xh, g_xh);   cudaGetSymbolAddress(&p_xl, g_xl);
    cudaGetSymbolAddress(&p_W1t, g_W1t); cudaGetSymbolAddress(&p_W2t, g_W2t);
    cudaGetSymbolAddress(&p_yh, g_yh);   cudaGetSymbolAddress(&p_yl, g_yl);

    cudaFuncSetAttribute(mma_gemm_kernel,
                         cudaFuncAttributeMaxDynamicSharedMemorySize, SMEM_GEMM);

    // 0) conversions
    split_x_kernel<<<2048, 256>>>(x, (__half*)p_xh, (__half*)p_xl,
                                  (size_t)MROWS * DMODEL / 4);
    {
        dim3 g1(PROJPAD / 32, DMODEL / 32);   // (132, 64)
        transpose_h_kernel<<<g1, 256>>>(W_in, (__half*)p_W1t, DMODEL, PROJ);
        dim3 g2(DMODEL / 32, DMODEL / 32);    // (64, 64)
        transpose_h_kernel<<<g2, 256>>>(W_out, (__half*)p_W2t, DMODEL, DMODEL);
    }
    // 1) proj = x @ W_in + b_in
    {
        dim3 grid(PROJPAD / BN, MROWS / BM);  // (33, 64)
        mma_gemm_kernel<<<grid, 256, SMEM_GEMM>>>(
            (const __half*)p_xh, (const __half*)p_xl, (const __half*)p_W1t,
            b_in, (float*)p_proj, PROJ);
    }
    // 2) conv + SiLU + dt/dA
    conv_dt_kernel<<<MROWS, 256>>>(conv_w, conv_b, A_log, dt_bias);
    // 3) selective scan
    scan_kernel<<<BATCH * HEADS, 256>>>();
    // 4) gated RMSNorm -> fp16 pair
    gated_rmsnorm_kernel<<<MROWS, 256>>>(D_param, norm_w);
    // 5) out = y @ W_out
    {
        dim3 grid(DMODEL / BN, MROWS / BM);   // (16, 64)
        mma_gemm_kernel<<<grid, 256, SMEM_GEMM>>>(
            (const __half*)p_yh, (const __half*)p_yl, (const __half*)p_W2t,
            nullptr, out, DMODEL);
    }
}

// round 13
// speedup vs baseline: 1.0047x; 1.0047x over previous
#include <cuda_runtime.h>
#include <cuda_bf16.h>
#include <cuda_fp16.h>
#include <math.h>
#include <stdint.h>

// ---------------- problem constants ----------------
#define BATCH   4
#define LEN     2048
#define HEADS   32
#define PDIM    64
#define NSTATE  32
#define KCONV   4
#define DMODEL  2048              // HEADS*PDIM
#define CONVDIM 2112              // DMODEL + 2*NSTATE
#define PROJ    4192              // DMODEL + CONVDIM + HEADS
#define PROJPAD 4224              // PROJ padded to 128 multiple
#define MROWS   (BATCH*LEN)       // 8192
#define EPS     1e-6f

// ---------------- scratch (static device globals) ----------------
__device__ float g_proj[(size_t)MROWS * PROJ];
__device__ float g_xs  [(size_t)MROWS * DMODEL];
__device__ float g_Bm  [MROWS * NSTATE];
__device__ float g_Cm  [MROWS * NSTATE];
__device__ float g_dt  [MROWS * HEADS];
__device__ float g_dA  [MROWS * HEADS];
__device__ float g_ys  [(size_t)MROWS * DMODEL];

__device__ __half g_xh [(size_t)MROWS * DMODEL];      // x hi (fp16)
__device__ __half g_xl [(size_t)MROWS * DMODEL];      // x residual (fp16)
__device__ __half g_W1t[(size_t)PROJPAD * DMODEL];    // W_in^T fp16
__device__ __half g_W2t[(size_t)DMODEL * DMODEL];     // W_out^T fp16
__device__ __half g_yh [(size_t)MROWS * DMODEL];      // y hi
__device__ __half g_yl [(size_t)MROWS * DMODEL];      // y residual

// ==================== PTX helpers ====================
__device__ __forceinline__ uint32_t smem_u32(const void* p) {
    uint32_t a;
    asm("{ .reg .u64 t; cvta.to.shared.u64 t, %1; cvt.u32.u64 %0, t; }"
        : "=r"(a) : "l"(p));
    return a;
}
__device__ __forceinline__ void cp16(uint32_t s, const void* g) {
    asm volatile("cp.async.cg.shared.global [%0], [%1], 16;" :: "r"(s), "l"(g));
}
#define CP_COMMIT() asm volatile("cp.async.commit_group;" ::: "memory")
#define CP_WAIT1()  asm volatile("cp.async.wait_group 1;"  ::: "memory")

__device__ __forceinline__ void ldsm4(uint32_t* r, uint32_t addr) {
    asm volatile("ldmatrix.sync.aligned.m8n8.x4.shared.b16 {%0,%1,%2,%3}, [%4];"
        : "=r"(r[0]), "=r"(r[1]), "=r"(r[2]), "=r"(r[3]) : "r"(addr));
}
__device__ __forceinline__ void mma16816(float* d, const uint32_t* a, const uint32_t* b) {
    asm volatile(
        "mma.sync.aligned.m16n8k16.row.col.f32.f16.f16.f32 "
        "{%0,%1,%2,%3}, {%4,%5,%6,%7}, {%8,%9}, {%0,%1,%2,%3};"
        : "+f"(d[0]), "+f"(d[1]), "+f"(d[2]), "+f"(d[3])
        : "r"(a[0]), "r"(a[1]), "r"(a[2]), "r"(a[3]), "r"(b[0]), "r"(b[1]));
}

// ==================== fp16 2-term tensor-core GEMM ====================
// C[M, Nreal] = A[M,K] @ W[K,N]; A = Ah + Al (fp16 pair, exact to 2^-22),
// B^T = Bh [N,K] fp16 (rounded). C = Ah*Bh + Al*Bh = A*Bh.
#define BM 128
#define BN 128
#define BK 32
#define LDS 40                    // smem row stride in fp16 (80 B) - conflict-free
#define TILE_B (BM * LDS * 2)     // 10240 bytes per matrix tile
#define STAGE_B (3 * TILE_B)      // 30720 bytes (Ah, Al, Bh)
#define NSTAGE 3
#define SMEM_GEMM (NSTAGE * STAGE_B)   // 92160 bytes

__device__ __forceinline__ void load_stage(
    uint32_t sbase, const __half* Ah, const __half* Al, const __half* Bh,
    int m0, int n0, int k0, int tid)
{
    const int row  = tid >> 1;
    const int half = tid & 1;
    const uint32_t soff = (uint32_t)(row * LDS + half * 16) * 2;   // bytes
    const size_t ga = (size_t)(m0 + row) * DMODEL + k0 + half * 16;
    const size_t gb = (size_t)(n0 + row) * DMODEL + k0 + half * 16;
    cp16(sbase + 0*TILE_B + soff,      Ah + ga);
    cp16(sbase + 0*TILE_B + soff + 16, Ah + ga + 8);
    cp16(sbase + 1*TILE_B + soff,      Al + ga);
    cp16(sbase + 1*TILE_B + soff + 16, Al + ga + 8);
    cp16(sbase + 2*TILE_B + soff,      Bh + gb);
    cp16(sbase + 2*TILE_B + soff + 16, Bh + gb + 8);
}

__global__ __launch_bounds__(256, 2)
void mma_gemm_kernel(const __half* __restrict__ Ah,
                     const __half* __restrict__ Al,
                     const __half* __restrict__ Bh,
                     const float* __restrict__ bias,
                     float* __restrict__ C, int Nreal)
{
    extern __shared__ char smem[];
    const uint32_t sb = smem_u32(smem);
    const int tid  = threadIdx.x;
    const int wid  = tid >> 5, lane = tid & 31;
    const int wm   = wid & 1;         // 2 m-warps (64 rows each)
    const int wn   = wid >> 1;        // 4 n-warps (32 cols each)
    const int m0   = blockIdx.y * BM;
    const int n0   = blockIdx.x * BN;

    // ldmatrix lane-relative byte offsets (verified in R6)
    const uint32_t a_loff = (uint32_t)((lane & 15) * LDS + (lane >> 4) * 8) * 2;
    const int b_q = lane >> 3, b_r = lane & 7;
    const uint32_t b_loff = (uint32_t)(((b_q >> 1) * 8 + b_r) * LDS + (b_q & 1) * 8) * 2;

    float acc[4][4][4];
    #pragma unroll
    for (int i = 0; i < 4; ++i)
        #pragma unroll
        for (int j = 0; j < 4; ++j)
            #pragma unroll
            for (int r = 0; r < 4; ++r) acc[i][j][r] = 0.f;

    load_stage(sb,           Ah, Al, Bh, m0, n0, 0,  tid); CP_COMMIT();
    load_stage(sb + STAGE_B, Ah, Al, Bh, m0, n0, BK, tid); CP_COMMIT();

    const int iters = DMODEL / BK;   // 64
    for (int it = 0; it < iters; ++it) {
        CP_WAIT1();                  // stage `it` complete; `it+1` may be in flight
        __syncthreads();             // also protects buffer (it+2)%3 == (it-1)%3

        // prefetch stage it+2 (overlaps with compute below)
        const int kn = (it + NSTAGE - 1) * BK;
        if (kn < DMODEL)
            load_stage(sb + (uint32_t)((it + NSTAGE - 1) % NSTAGE) * STAGE_B,
                       Ah, Al, Bh, m0, n0, kn, tid);
        CP_COMMIT();

        const uint32_t base = sb + (uint32_t)(it % NSTAGE) * STAGE_B;
        const uint32_t aAh  = base + (uint32_t)(wm * 64 * LDS) * 2 + a_loff;
        const uint32_t aAl  = aAh + TILE_B;
        const uint32_t bBh  = base + 2*TILE_B + (uint32_t)(wn * 32 * LDS) * 2 + b_loff;

        #pragma unroll
        for (int ks = 0; ks < 2; ++ks) {
            const uint32_t koff = ks * 32;           // 16 fp16 = 32 bytes
            uint32_t bh[4][2];
            #pragma unroll
            for (int jp = 0; jp < 2; ++jp) {
                uint32_t t4[4];
                ldsm4(t4, bBh + (uint32_t)(jp * 16 * LDS) * 2 + koff);
                bh[2*jp][0]   = t4[0]; bh[2*jp][1]   = t4[1];
                bh[2*jp+1][0] = t4[2]; bh[2*jp+1][1] = t4[3];
            }
            #pragma unroll
            for (int i = 0; i < 4; ++i) {
                uint32_t ah[4], al[4];
                ldsm4(ah, aAh + (uint32_t)(i * 16 * LDS) * 2 + koff);
                ldsm4(al, aAl + (uint32_t)(i * 16 * LDS) * 2 + koff);
                #pragma unroll
                for (int j = 0; j < 4; ++j) {
                    mma16816(acc[i][j], ah, bh[j]);
                    mma16816(acc[i][j], al, bh[j]);
                }
            }
        }
    }

    // ---- epilogue ----
    const int r0 = lane >> 2;
    const int c0 = (lane & 3) * 2;
    #pragma unroll
    for (int i = 0; i < 4; ++i) {
        const int row = m0 + wm * 64 + i * 16 + r0;
        #pragma unroll
        for (int j = 0; j < 4; ++j) {
            const int col = n0 + wn * 32 + j * 8 + c0;
            if (col < Nreal) {
                float b0 = 0.f, b1 = 0.f;
                if (bias) { b0 = bias[col]; b1 = bias[col + 1]; }
                float* p0 = C + (size_t)row * Nreal + col;
                float* p1 = C + (size_t)(row + 8) * Nreal + col;
                p0[0] = acc[i][j][0] + b0;  p0[1] = acc[i][j][1] + b1;
                p1[0] = acc[i][j][2] + b0;  p1[1] = acc[i][j][3] + b1;
            }
        }
    }
}

// ==================== fp16 split conversions ====================
// x fp32 -> xh + xl (fp16 pair)
__global__ __launch_bounds__(256)
void split_x_kernel(const float* __restrict__ src, __half* __restrict__ h,
                    __half* __restrict__ l, size_t n4)
{
    const size_t stride = (size_t)gridDim.x * blockDim.x;
    for (size_t i = (size_t)blockIdx.x * blockDim.x + threadIdx.x; i < n4; i += stride) {
        float4 v = reinterpret_cast<const float4*>(src)[i];
        __half h0 = __float2half_rn(v.x), h1 = __float2half_rn(v.y);
        __half h2 = __float2half_rn(v.z), h3 = __float2half_rn(v.w);
        __half2* hp = reinterpret_cast<__half2*>(h);
        __half2* lp = reinterpret_cast<__half2*>(l);
        hp[i*2]   = __half2(h0, h1);
        hp[i*2+1] = __half2(h2, h3);
        lp[i*2]   = __half2(__float2half_rn(v.x - __half2float(h0)),
                            __float2half_rn(v.y - __half2float(h1)));
        lp[i*2+1] = __half2(__float2half_rn(v.z - __half2float(h2)),
                            __float2half_rn(v.w - __half2float(h3)));
    }
}

// W[K,N] fp32 -> Wt [Npad,K] fp16 (transpose, zero pad rows n>=N)
__global__ __launch_bounds__(256)
void transpose_h_kernel(const float* __restrict__ W,
                        __half* __restrict__ th, int K, int N)
{
    __shared__ float t[32][33];
    const int n0 = blockIdx.x * 32;
    const int k0 = blockIdx.y * 32;
    const int tx = threadIdx.x & 31;
    const int ty = threadIdx.x >> 5;
    #pragma unroll
    for (int i = 0; i < 4; ++i) {
        const int k = k0 + ty + i * 8;
        const int n = n0 + tx;
        t[ty + i * 8][tx] = (n < N) ? W[(size_t)k * N + n] : 0.f;
    }
    __syncthreads();
    #pragma unroll
    for (int i = 0; i < 4; ++i) {
        const int n = n0 + ty + i * 8;
        const int k = k0 + tx;
        th[(size_t)n * K + k] = __float2half_rn(t[tx][ty + i * 8]);
    }
}

// ==================== conv + dt, scan, rmsnorm ====================
__device__ __forceinline__ float silu_f(float x) { return x / (1.f + expf(-x)); }
__device__ __forceinline__ float softplus_f(float x) {
    return x > 20.f ? x : log1pf(expf(x));
}

__global__ void conv_dt_kernel(const float* __restrict__ conv_w,
                               const float* __restrict__ conv_b,
                               const float* __restrict__ A_log,
                               const float* __restrict__ dt_bias)
{
    const int m = blockIdx.x;
    const int l = m & (LEN - 1);
    for (int c = threadIdx.x; c < CONVDIM + HEADS; c += blockDim.x) {
        if (c < CONVDIM) {
            float v = conv_b[c];
            const size_t colbase = (size_t)DMODEL + c;
            #pragma unroll
            for (int k = 0; k < KCONV; ++k) {
                int dl = l - (KCONV - 1) + k;
                if (dl >= 0) {
                    float hv = g_proj[(size_t)(m - (KCONV - 1) + k) * PROJ + colbase];
                    v = fmaf(hv, conv_w[c * KCONV + k], v);
                }
            }
            v = silu_f(v);
            if (c < DMODEL)               g_xs[(size_t)m * DMODEL + c] = v;
            else if (c < DMODEL + NSTATE) g_Bm[m * NSTATE + (c - DMODEL)] = v;
            else                          g_Cm[m * NSTATE + (c - DMODEL - NSTATE)] = v;
        } else {
            const int h = c - CONVDIM;
            float raw = g_proj[(size_t)m * PROJ + (DMODEL + CONVDIM) + h] + dt_bias[h];
            float dt  = softplus_f(raw);
            float A   = -expf(A_log[h]);
            g_dt[m * HEADS + h] = dt;
            g_dA[m * HEADS + h] = expf(dt * A);
        }
    }
}

__global__ __launch_bounds__(256, 4)
void scan_kernel()
{
    const int b = blockIdx.x >> 5;
    const int h = blockIdx.x & 31;
    const int tid = threadIdx.x;
    const int p  = tid >> 2;
    const int ng = tid & 3;

    __shared__ float sx[2][PDIM];
    __shared__ float sB[2][NSTATE];
    __shared__ float sC[2][NSTATE];
    __shared__ float sS[2][2];

    float hreg[8];
    #pragma unroll
    for (int j = 0; j < 8; ++j) hreg[j] = 0.f;

    const int baseRow = b * LEN;
    {
        const int m = baseRow;
        if (tid < 64)        sx[0][tid]      = g_xs[(size_t)m * DMODEL + h * PDIM + tid];
        else if (tid < 96)   sB[0][tid - 64] = g_Bm[m * NSTATE + tid - 64];
        else if (tid < 128)  sC[0][tid - 96] = g_Cm[m * NSTATE + tid - 96];
        else if (tid == 128) sS[0][0]        = g_dA[m * HEADS + h];
        else if (tid == 129) sS[0][1]        = g_dt[m * HEADS + h];
    }
    __syncthreads();

    for (int t = 0; t < LEN; ++t) {
        const int buf = t & 1;
        if (t + 1 < LEN) {
            const int m = baseRow + t + 1;
            const int nb = buf ^ 1;
            if (tid < 64)        sx[nb][tid]      = g_xs[(size_t)m * DMODEL + h * PDIM + tid];
            else if (tid < 96)   sB[nb][tid - 64] = g_Bm[m * NSTATE + tid - 64];
            else if (tid < 128)  sC[nb][tid - 96] = g_Cm[m * NSTATE + tid - 96];
            else if (tid == 128) sS[nb][0]        = g_dA[m * HEADS + h];
            else if (tid == 129) sS[nb][1]        = g_dt[m * HEADS + h];
        }
        const float a   = sS[buf][0];
        const float dtx = sS[buf][1] * sx[buf][p];
        float acc = 0.f;
        #pragma unroll
        for (int j = 0; j < 8; ++j) {
            const int n = ng * 8 + j;
            hreg[j] = fmaf(a, hreg[j], dtx * sB[buf][n]);
            acc = fmaf(hreg[j], sC[buf][n], acc);
        }
        acc += __shfl_xor_sync(0xffffffffu, acc, 1);
        acc += __shfl_xor_sync(0xffffffffu, acc, 2);
        if (ng == 0)
            g_ys[(size_t)(baseRow + t) * DMODEL + h * PDIM + p] = acc;
        __syncthreads();
    }
}

// y = ys + D*xs ; gate ; RMSNorm ; emit fp16 hi/lo pair (feeds GEMM2)
__global__ __launch_bounds__(256)
void gated_rmsnorm_kernel(const float* __restrict__ D_param,
                          const float* __restrict__ norm_w)
{
    const int m = blockIdx.x;
    const int tid = threadIdx.x;
    float v[8];
    float ss = 0.f;

    #pragma unroll
    for (int i = 0; i < 8; ++i) {
        const int d = tid + i * 256;
        const int h = d >> 6;
        float val = g_ys[(size_t)m * DMODEL + d] + D_param[h] * g_xs[(size_t)m * DMODEL + d];
        float g   = g_proj[(size_t)m * PROJ + d];
        val *= silu_f(g);
        v[i] = val;
        ss = fmaf(val, val, ss);
    }
    #pragma unroll
    for (int o = 16; o > 0; o >>= 1) ss += __shfl_xor_sync(0xffffffffu, ss, o);
    __shared__ float red[8];
    if ((tid & 31) == 0) red[tid >> 5] = ss;
    __syncthreads();
    if (tid < 32) {
        float t2 = (tid < 8) ? red[tid] : 0.f;
        #pragma unroll
        for (int o = 4; o > 0; o >>= 1) t2 += __shfl_xor_sync(0xffffffffu, t2, o);
        if (tid == 0) red[0] = t2;
    }
    __syncthreads();
    const float scale = rsqrtf(red[0] / (float)DMODEL + EPS);

    #pragma unroll
    for (int i = 0; i < 8; ++i) {
        const int d = tid + i * 256;
        const float y = v[i] * scale * norm_w[d];
        const __half hh = __float2half_rn(y);
        g_yh[(size_t)m * DMODEL + d] = hh;
        g_yl[(size_t)m * DMODEL + d] = __float2half_rn(y - __half2float(hh));
    }
}

// ==================== host launcher ====================
extern "C" void kernel_launch(void* const* d_in, const int* in_sizes, int n_in,
                              void* d_out, int out_size)
{
    const float* x       = (const float*)d_in[0];
    const float* W_in    = (const float*)d_in[1];
    const float* b_in    = (const float*)d_in[2];
    const float* conv_w  = (const float*)d_in[3];
    const float* conv_b  = (const float*)d_in[4];
    const float* A_log   = (const float*)d_in[5];
    const float* dt_bias = (const float*)d_in[6];
    const float* D_param = (const float*)d_in[7];
    const float* norm_w  = (const float*)d_in[8];
    const float* W_out   = (const float*)d_in[9];
    float* out = (float*)d_out;

    void *p_proj, *p_xh, *p_xl, *p_W1t, *p_W2t, *p_yh, *p_yl;
    cudaGetSymbolAddress(&p_proj, g_proj);
    cudaGetSymbolAddress(&p_xh, g_xh);   cudaGetSymbolAddress(&p_xl, g_xl);
    cudaGetSymbolAddress(&p_W1t, g_W1t); cudaGetSymbolAddress(&p_W2t, g_W2t);
    cudaGetSymbolAddress(&p_yh, g_yh);   cudaGetSymbolAddress(&p_yl, g_yl);

    cudaFuncSetAttribute(mma_gemm_kernel,
                         cudaFuncAttributeMaxDynamicSharedMemorySize, SMEM_GEMM);

    // 0) conversions
    split_x_kernel<<<2048, 256>>>(x, (__half*)p_xh, (__half*)p_xl,
                                  (size_t)MROWS * DMODEL / 4);
    {
        dim3 g1(PROJPAD / 32, DMODEL / 32);   // (132, 64)
        transpose_h_kernel<<<g1, 256>>>(W_in, (__half*)p_W1t, DMODEL, PROJ);
        dim3 g2(DMODEL / 32, DMODEL / 32);    // (64, 64)
        transpose_h_kernel<<<g2, 256>>>(W_out, (__half*)p_W2t, DMODEL, DMODEL);
    }
    // 1) proj = x @ W_in + b_in
    {
        dim3 grid(PROJPAD / BN, MROWS / BM);  // (33, 64)
        mma_gemm_kernel<<<grid, 256, SMEM_GEMM>>>(
            (const __half*)p_xh, (const __half*)p_xl, (const __half*)p_W1t,
            b_in, (float*)p_proj, PROJ);
    }
    // 2) conv + SiLU + dt/dA
    conv_dt_kernel<<<MROWS, 256>>>(conv_w, conv_b, A_log, dt_bias);
    // 3) selective scan
    scan_kernel<<<BATCH * HEADS, 256>>>();
    // 4) gated RMSNorm -> fp16 pair
    gated_rmsnorm_kernel<<<MROWS, 256>>>(D_param, norm_w);
    // 5) out = y @ W_out
    {
        dim3 grid(DMODEL / BN, MROWS / BM);   // (16, 64)
        mma_gemm_kernel<<<grid, 256, SMEM_GEMM>>>(
            (const __half*)p_yh, (const __half*)p_yl, (const __half*)p_W2t,
            nullptr, out, DMODEL);
    }
}